// round 15
// baseline (speedup 1.0000x reference)
#include <cuda_runtime.h>
#include <cuda_fp16.h>
#include <math_constants.h>
#include <cstdint>

#define N      8192
#define D      128
#define THR    1e-4f
#define SPLIT  8
#define BK     32
#define JR     (N / SPLIT)          // 1024 j per agg unit
#define NT     (JR / BK)            // 32 K-iterations per unit
#define MB     32                   // i-rows per agg unit
#define NIB    (N / MB)             // 256 i-blocks
#define NUNITS (NIB * SPLIT)        // 2048 agg units
#define SROWS  8
#define NSTAT  (N / SROWS)          // 1024 stats blocks
#define NCTA   296                  // 148 x 2, ALL resident (spin safety)

// ---------------- scratch (static device globals; no allocation) ------------
__device__ float    g_h[N * D];                    // 4 MB fp32 h (residual)
__device__ float    g_src[N], g_Bz[N], g_Cz[N];
__device__ float4   g_rowc[N];                     // {eaF, ebF, T3, -}
__device__ unsigned g_mask[(size_t)N * N / 32];    // 8 MB adjacency bits
__device__ __align__(16) __half g_hh[N * D];       // 2 MB h (fp16)
__device__ float    g_part[SPLIT][N * D];          // 32 MB split-K partials
__device__ unsigned g_ctr;                         // work-steal counter
__device__ int      g_done[NSTAT];                 // stats ready flags

// smem tile geometry (16-bit pitches; odd 16B-granule counts -> LDSM clean)
#define APITCH 40
#define BPITCH 136
#define A_BYTES (MB * APITCH * 2)                  // 2560
#define B_BYTES (BK * BPITCH * 2)                  // 8704
#define BUF_BYTES (A_BYTES + B_BYTES)              // 11264
#define SM_TAB    (2 * BUF_BYTES)                  // 22528
#define SMEM_DYN  (SM_TAB + 2 * JR * 4)            // 30720

// ---------------- PTX helpers -----------------------------------------------
__device__ __forceinline__ uint32_t smem_u32(const void* p) {
    uint32_t a;
    asm("{ .reg .u64 t; cvta.to.shared.u64 t, %1; cvt.u32.u64 %0, t; }"
        : "=r"(a) : "l"(p));
    return a;
}
__device__ __forceinline__ void cpa16(uint32_t dst, const void* src) {
    asm volatile("cp.async.cg.shared.global [%0], [%1], 16;"
                 :: "r"(dst), "l"(src) : "memory");
}
#define CPA_COMMIT() asm volatile("cp.async.commit_group;" ::: "memory")
#define CPA_WAIT0()  asm volatile("cp.async.wait_group 0;" ::: "memory")

__device__ __forceinline__ void ldsm4(uint32_t* r, uint32_t addr) {
    asm volatile("ldmatrix.sync.aligned.m8n8.x4.shared.b16 {%0,%1,%2,%3}, [%4];"
                 : "=r"(r[0]), "=r"(r[1]), "=r"(r[2]), "=r"(r[3]) : "r"(addr));
}
__device__ __forceinline__ void ldsm4t(uint32_t* r, uint32_t addr) {
    asm volatile("ldmatrix.sync.aligned.m8n8.x4.trans.shared.b16 {%0,%1,%2,%3}, [%4];"
                 : "=r"(r[0]), "=r"(r[1]), "=r"(r[2]), "=r"(r[3]) : "r"(addr));
}
__device__ __forceinline__ void mma16816(float* c, const uint32_t* a,
                                         const uint32_t* b) {
    asm volatile("mma.sync.aligned.m16n8k16.row.col.f32.f16.f16.f32 "
                 "{%0,%1,%2,%3}, {%4,%5,%6,%7}, {%8,%9}, {%0,%1,%2,%3};"
                 : "+f"(c[0]), "+f"(c[1]), "+f"(c[2]), "+f"(c[3])
                 : "r"(a[0]), "r"(a[1]), "r"(a[2]), "r"(a[3]),
                   "r"(b[0]), "r"(b[1]));
}
__device__ __forceinline__ int ld_acquire(const int* p) {
    int v;
    asm volatile("ld.acquire.gpu.global.b32 %0, [%1];" : "=r"(v) : "l"(p) : "memory");
    return v;
}
__device__ __forceinline__ void st_release(int* p, int v) {
    asm volatile("st.release.gpu.global.b32 [%0], %1;" :: "l"(p), "r"(v) : "memory");
}

// ---------------- K1: h = X @ W + per-node scalars + fp16 -------------------
__global__ void k_h(const float* __restrict__ x,
                    const float* __restrict__ W,
                    const float* __restrict__ a) {
    int i = blockIdx.x;
    int k = threadIdx.x;

    if (k == 0) {
        if (i == 0) g_ctr = 0;
        if (i < NSTAT) g_done[i] = 0;
    }

    __shared__ float xs[D];
    __shared__ float red[D];
    __shared__ float res[3];

    xs[k] = x[i * D + k];
    __syncthreads();

    float acc = 0.f;
#pragma unroll 16
    for (int c = 0; c < D; ++c)
        acc = fmaf(xs[c], W[c * D + k], acc);

    g_h[i * D + k]  = acc;
    g_hh[i * D + k] = __float2half_rn(acc);

    float vals[3] = {acc, acc * a[k], acc * a[D + k]};
#pragma unroll
    for (int v = 0; v < 3; ++v) {
        red[k] = vals[v];
        __syncthreads();
        for (int st = 64; st > 0; st >>= 1) {
            if (k < st) red[k] += red[k + st];
            __syncthreads();
        }
        if (k == 0) res[v] = red[0];
        __syncthreads();
    }
    if (k == 0) {
        float rs = res[0], s = res[1], d = res[2];
        bool  nz = (rs != 0.0f);
        g_src[i] = s;
        g_Bz[i]  = nz ? __expf(d)        : 0.f;
        g_Cz[i]  = nz ? __expf(0.2f * d) : 0.f;
    }
}

// ---------------- K2: fused persistent stats + MMA kernel -------------------
// steal order: units [0, NSTAT) = stats blocks; [NSTAT, NSTAT+NUNITS) = agg.
// agg units iblock-major so early agg needs early stats rows only.
__global__ void __launch_bounds__(256, 2) k_fused(const int* __restrict__ adj) {
    extern __shared__ __align__(16) char sm[];
    __shared__ unsigned s_u;
    uint32_t smb = smem_u32(sm);

    int tid  = threadIdx.x;
    int lane = tid & 31;
    int wid  = tid >> 5;

    float* s_bz = (float*)(sm + SM_TAB);
    float* s_cz = s_bz + JR;

    // agg thread roles
    int gi = tid >> 3;            // gen row within i-block (0..31)
    int j4 = (tid & 7) << 2;      // gen 4-j slice within BK
    int wm = (wid & 1) * 16;      // mma warp tile: 2 x 4 grid of 16m x 32n
    int wn = (wid >> 1) * 32;

    while (true) {
        if (tid == 0) s_u = atomicAdd(&g_ctr, 1u);
        __syncthreads();
        unsigned u = s_u;

        if (u < NSTAT) {
            // ================= stats block: SROWS rows =======================
            int row = u * SROWS + wid;
            float src = g_src[row];
            float ea  = __expf(src);
            float eb  = __expf(0.2f * src);

            float s = 0.f, vm = 0.f;
            int   cnt = 0;
            const int4* arow = (const int4*)(adj + (size_t)row * N);
            unsigned* mrow = g_mask + (size_t)row * (N / 32);

            for (int blk4 = 0; blk4 < N / 512; ++blk4) {
                int4 av[4];
#pragma unroll
                for (int q = 0; q < 4; ++q)
                    av[q] = arow[blk4 * 128 + q * 32 + lane];
#pragma unroll
                for (int q = 0; q < 4; ++q) {
                    int blk = blk4 * 4 + q;
                    int j0  = blk * 128 + lane * 4;
                    float4 bz = __ldg((const float4*)(g_Bz + j0));
                    float4 cz = __ldg((const float4*)(g_Cz + j0));

                    unsigned nib = (av[q].x > 0) | ((av[q].y > 0) << 1) |
                                   ((av[q].z > 0) << 2) | ((av[q].w > 0) << 3);
                    unsigned v = nib;
                    v |= __shfl_down_sync(0xffffffffu, v, 1) << 4;
                    v |= __shfl_down_sync(0xffffffffu, v, 2) << 8;
                    v |= __shfl_down_sync(0xffffffffu, v, 4) << 16;
                    if ((lane & 7) == 0)
                        mrow[blk * 4 + (lane >> 3)] = v;

                    float ba[4] = {bz.x, bz.y, bz.z, bz.w};
                    float ca[4] = {cz.x, cz.y, cz.z, cz.w};
#pragma unroll
                    for (int t = 0; t < 4; ++t) {
                        float vv  = fmaxf(ea * ba[t], eb * ca[t]);
                        bool  bit = (nib >> t) & 1u;
                        float val = bit ? vv : 0.f;
                        s  += val;
                        vm  = fmaxf(vm, val);
                        cnt += (bit && vv > 0.f) ? 1 : 0;
                    }
                }
            }
#pragma unroll
            for (int o = 16; o > 0; o >>= 1) {
                s   += __shfl_xor_sync(0xffffffffu, s, o);
                vm   = fmaxf(vm, __shfl_xor_sync(0xffffffffu, vm, o));
                cnt += __shfl_xor_sync(0xffffffffu, cnt, o);
            }
            if (lane == 0) {
                bool active = (vm > THR * s);
                float eaF = 0.f, ebF = 0.f, T3 = CUDART_INF_F;
                if (active) {
                    float F = (float)cnt / s;
                    eaF = ea * F;
                    ebF = eb * F;
                    T3  = THR * (float)cnt;
                }
                g_rowc[row] = make_float4(eaF, ebF, T3, 0.f);
            }
            __threadfence();
            __syncthreads();
            if (tid == 0) st_release(&g_done[u], 1);
            continue;
        }

        unsigned v = u - NSTAT;
        if (v >= NUNITS) break;

        // ================= agg unit ==========================================
        int iblock = v >> 3;          // iblock-major
        int split  = v & 7;
        int ib     = iblock * MB;
        int jstart = split * JR;

        // wait for stats of rows [ib, ib+MB)
        if (tid == 0) {
            int f0 = ib / SROWS;
#pragma unroll
            for (int q = 0; q < MB / SROWS; ++q)
                while (ld_acquire(&g_done[f0 + q]) == 0) __nanosleep(64);
        }
        __syncthreads();

        float4 rc = g_rowc[ib + gi];
        const unsigned* mrow =
            g_mask + (size_t)(ib + gi) * (N / 32) + (jstart >> 5);

        float acc[4][4];
#pragma unroll
        for (int nf = 0; nf < 4; ++nf)
#pragma unroll
            for (int q = 0; q < 4; ++q) acc[nf][q] = 0.f;

        auto loadB = [&](int t) {
            int b  = t & 1;
            int jb = jstart + t * BK;
            uint32_t Bh = smb + b * BUF_BYTES + A_BYTES;
#pragma unroll
            for (int q = 0; q < 2; ++q) {
                int idx = tid + q * 256;
                int r = idx >> 4, g = idx & 15;
                uint32_t doff = (uint32_t)(r * BPITCH + g * 8) * 2;
                cpa16(Bh + doff, g_hh + (size_t)(jb + r) * D + g * 8);
            }
            CPA_COMMIT();
        };

        auto gen_store = [&](int t, unsigned mw_word) {
            int b = t & 1;
            char* Ah = sm + b * BUF_BYTES;
            unsigned mw = mw_word >> j4;
            int lj = t * BK + j4;
            float4 bz = *(const float4*)(s_bz + lj);
            float4 cz = *(const float4*)(s_cz + lj);
            float ba[4] = {bz.x, bz.y, bz.z, bz.w};
            float ca[4] = {cz.x, cz.y, cz.z, cz.w};
            float w[4];
#pragma unroll
            for (int k = 0; k < 4; ++k) {
                float vv = fmaxf(rc.x * ba[k], rc.y * ca[k]);
                bool ok  = (vv >= rc.z) && ((mw >> k) & 1u);
                w[k] = ok ? vv : 0.f;
            }
            uint32_t p0, p1;
            asm("cvt.rn.f16x2.f32 %0, %1, %2;" : "=r"(p0) : "f"(w[1]), "f"(w[0]));
            asm("cvt.rn.f16x2.f32 %0, %1, %2;" : "=r"(p1) : "f"(w[3]), "f"(w[2]));
            uint32_t* a32 = (uint32_t*)Ah + gi * (APITCH / 2) + (j4 >> 1);
            *(uint2*)a32 = make_uint2(p0, p1);
        };

        auto domma = [&](int t) {
            int b = t & 1;
            uint32_t Ah = smb + b * BUF_BYTES;
            uint32_t Bh = Ah + A_BYTES;
#pragma unroll
            for (int ks = 0; ks < 2; ++ks) {
                int k0 = ks * 16;
                uint32_t af[4];
                {
                    uint32_t row = wm + (lane & 15);
                    uint32_t off = row * (APITCH * 2) + (k0 + ((lane >> 4) << 3)) * 2;
                    ldsm4(af, Ah + off);
                }
#pragma unroll
                for (int nf2 = 0; nf2 < 2; ++nf2) {
                    int n0 = wn + nf2 * 16;
                    uint32_t r = k0 + (lane & 7) + ((lane >> 3) & 1) * 8;
                    uint32_t c = n0 + ((lane >> 4) << 3);
                    uint32_t off = r * (BPITCH * 2) + c * 2;
                    uint32_t bh[4];
                    ldsm4t(bh, Bh + off);
                    mma16816(acc[nf2 * 2],     af, bh);
                    mma16816(acc[nf2 * 2 + 1], af, bh + 2);
                }
            }
        };

        // ---- unit prologue: B(0) async + stage tables + A(0) -----------------
        loadB(0);
#pragma unroll
        for (int q = 0; q < 2; ++q) {
            int idx = tid + q * 256;
            if (idx < 256)
                ((float4*)s_bz)[idx] = __ldg((const float4*)(g_Bz + jstart) + idx);
            else
                ((float4*)s_cz)[idx - 256] =
                    __ldg((const float4*)(g_Cz + jstart) + (idx - 256));
        }
        __syncthreads();
        gen_store(0, __ldg(&mrow[0]));

        // ---- pipeline --------------------------------------------------------
        for (int t = 0; t < NT; ++t) {
            CPA_WAIT0();
            __syncthreads();
            unsigned mwn = 0;
            if (t + 1 < NT) {
                mwn = __ldg(&mrow[t + 1]);
                loadB(t + 1);
            }
            domma(t);
            if (t + 1 < NT) gen_store(t + 1, mwn);
        }

        // ---- epilogue: write split partial -----------------------------------
        int r0    = ib + wm + (lane >> 2);
        int cbase = wn + (lane & 3) * 2;
#pragma unroll
        for (int nf = 0; nf < 4; ++nf) {
            int col = cbase + nf * 8;
            float* p = &g_part[split][(size_t)r0 * D + col];
            *(float2*)p           = make_float2(acc[nf][0], acc[nf][1]);
            *(float2*)(p + 8 * D) = make_float2(acc[nf][2], acc[nf][3]);
        }
        __syncthreads();   // all buffer reads done before next unit overwrites
    }
}

// ---------------- K3: combine partials + residual + ELU ---------------------
__global__ void k_out(float* __restrict__ out) {
    int g = blockIdx.x * blockDim.x + threadIdx.x;
    float4 v = ((const float4*)g_h)[g];
#pragma unroll
    for (int s = 0; s < SPLIT; ++s) {
        float4 p = __ldg((const float4*)g_part[s] + g);
        v.x += p.x; v.y += p.y; v.z += p.z; v.w += p.w;
    }
    float4 o;
    o.x = (v.x > 0.f) ? v.x : expm1f(v.x);
    o.y = (v.y > 0.f) ? v.y : expm1f(v.y);
    o.z = (v.z > 0.f) ? v.z : expm1f(v.z);
    o.w = (v.w > 0.f) ? v.w : expm1f(v.w);
    ((float4*)out)[g] = o;
}

// ---------------- launch ----------------------------------------------------
extern "C" void kernel_launch(void* const* d_in, const int* in_sizes, int n_in,
                              void* d_out, int out_size) {
    (void)in_sizes; (void)n_in; (void)out_size;
    const float* x   = (const float*)d_in[0];
    const float* W   = (const float*)d_in[1];
    const float* a   = (const float*)d_in[2];
    const int*   adj = (const int*)d_in[3];
    float*       out = (float*)d_out;

    cudaFuncSetAttribute(k_fused, cudaFuncAttributeMaxDynamicSharedMemorySize, SMEM_DYN);

    k_h    <<<N, 128>>>(x, W, a);
    k_fused<<<NCTA, 256, SMEM_DYN>>>(adj);
    k_out  <<<(N * D) / 1024, 256>>>(out);
}

// round 16
// speedup vs baseline: 1.3198x; 1.3198x over previous
#include <cuda_runtime.h>
#include <cuda_fp16.h>
#include <math_constants.h>
#include <cstdint>

#define N      8192
#define D      128
#define THR    1e-4f
#define SPLIT  16
#define BK     32
#define JR     (N / SPLIT)          // 512 j per unit
#define NT     (JR / BK)            // 16 K-iterations per unit
#define MB     64                   // i-rows per unit
#define NIB    (N / MB)             // 128 i-blocks
#define NUNITS (NIB * SPLIT)        // 2048 work units
#define NCTA   444                  // 148 SMs x 3
#define SROWS  8

// ---------------- scratch (static device globals; no allocation) ------------
__device__ float    g_h[N * D];                    // 4 MB fp32 h (residual)
__device__ float    g_src[N], g_Bz[N], g_Cz[N];
__device__ float4   g_rowc[N];                     // {eaF, ebF, T3, -}
__device__ unsigned g_mask[(size_t)N * N / 32];    // 8 MB adjacency bits
__device__ __align__(16) __half g_hh[N * D];       // 2 MB h (fp16)
__device__ float    g_part[SPLIT][N * D];          // 64 MB split-K partials
__device__ unsigned g_ctr;                         // work-steal counter

// k_agg smem tile geometry
#define APITCH 40
#define BPITCH 136
#define A_BYTES (MB * APITCH * 2)                  // 5120
#define B_BYTES (BK * BPITCH * 2)                  // 8704
#define BUF_BYTES (A_BYTES + B_BYTES)              // 13824
#define SM_TAB    (2 * BUF_BYTES)                  // 27648
#define SMEM_DYN  (SM_TAB + 2 * JR * 4)            // 31744 -> 3 CTAs/SM

// k_h smem: W (64KB) + X tile (32KB)
#define KH_ROWS   64
#define KH_SMEM   ((D * D + KH_ROWS * D) * 4)      // 98304

// ---------------- PTX helpers -----------------------------------------------
__device__ __forceinline__ uint32_t smem_u32(const void* p) {
    uint32_t a;
    asm("{ .reg .u64 t; cvta.to.shared.u64 t, %1; cvt.u32.u64 %0, t; }"
        : "=r"(a) : "l"(p));
    return a;
}
__device__ __forceinline__ void cpa16(uint32_t dst, const void* src) {
    asm volatile("cp.async.cg.shared.global [%0], [%1], 16;"
                 :: "r"(dst), "l"(src) : "memory");
}
#define CPA_COMMIT() asm volatile("cp.async.commit_group;" ::: "memory")
#define CPA_WAIT0()  asm volatile("cp.async.wait_group 0;" ::: "memory")

__device__ __forceinline__ void ldsm4(uint32_t* r, uint32_t addr) {
    asm volatile("ldmatrix.sync.aligned.m8n8.x4.shared.b16 {%0,%1,%2,%3}, [%4];"
                 : "=r"(r[0]), "=r"(r[1]), "=r"(r[2]), "=r"(r[3]) : "r"(addr));
}
__device__ __forceinline__ void ldsm4t(uint32_t* r, uint32_t addr) {
    asm volatile("ldmatrix.sync.aligned.m8n8.x4.trans.shared.b16 {%0,%1,%2,%3}, [%4];"
                 : "=r"(r[0]), "=r"(r[1]), "=r"(r[2]), "=r"(r[3]) : "r"(addr));
}
__device__ __forceinline__ void mma16816(float* c, const uint32_t* a,
                                         const uint32_t* b) {
    asm volatile("mma.sync.aligned.m16n8k16.row.col.f32.f16.f16.f32 "
                 "{%0,%1,%2,%3}, {%4,%5,%6,%7}, {%8,%9}, {%0,%1,%2,%3};"
                 : "+f"(c[0]), "+f"(c[1]), "+f"(c[2]), "+f"(c[3])
                 : "r"(a[0]), "r"(a[1]), "r"(a[2]), "r"(a[3]),
                   "r"(b[0]), "r"(b[1]));
}

// ---------------- K1: h = X @ W (W staged in smem) + per-node scalars --------
__global__ void __launch_bounds__(256) k_h(const float* __restrict__ x,
                                           const float* __restrict__ W,
                                           const float* __restrict__ a) {
    extern __shared__ __align__(16) float smf[];
    float* sW = smf;                 // [D][D]  64 KB
    float* sX = smf + D * D;         // [KH_ROWS][D] 32 KB

    int tid  = threadIdx.x;
    int lane = tid & 31;
    int ib   = blockIdx.x * KH_ROWS;

    if (blockIdx.x == 0 && tid == 0) g_ctr = 0;

    // stage W (16384 floats) and X tile (8192 floats)
#pragma unroll
    for (int q = 0; q < 16; ++q)
        ((float4*)sW)[tid + q * 256] = __ldg((const float4*)W + tid + q * 256);
#pragma unroll
    for (int q = 0; q < 8; ++q)
        ((float4*)sX)[tid + q * 256] =
            __ldg((const float4*)(x + (size_t)ib * D) + tid + q * 256);
    __syncthreads();

    // thread tile: 4 rows x 8 cols
    int grp = tid >> 4;              // 0..15 (16-thread group; half-warp aligned)
    int r0  = grp * 4;               // local row base
    int k0  = (tid & 15) * 8;        // col base

    float a_s[8], a_d[8];
#pragma unroll
    for (int u = 0; u < 8; ++u) {
        a_s[u] = __ldg(&a[k0 + u]);
        a_d[u] = __ldg(&a[D + k0 + u]);
    }

    float acc[4][8];
#pragma unroll
    for (int r = 0; r < 4; ++r)
#pragma unroll
        for (int u = 0; u < 8; ++u) acc[r][u] = 0.f;

#pragma unroll 4
    for (int c = 0; c < D; ++c) {
        float4 w0 = *(const float4*)(sW + c * D + k0);
        float4 w1 = *(const float4*)(sW + c * D + k0 + 4);
        float wv[8] = {w0.x, w0.y, w0.z, w0.w, w1.x, w1.y, w1.z, w1.w};
#pragma unroll
        for (int r = 0; r < 4; ++r) {
            float xv = sX[(r0 + r) * D + c];
#pragma unroll
            for (int u = 0; u < 8; ++u)
                acc[r][u] = fmaf(xv, wv[u], acc[r][u]);
        }
    }

    // write h (fp32 + fp16) and do per-row reductions via width-16 shuffles
#pragma unroll
    for (int r = 0; r < 4; ++r) {
        int row = ib + r0 + r;
        float* ph = g_h + (size_t)row * D + k0;
        *(float4*)ph       = make_float4(acc[r][0], acc[r][1], acc[r][2], acc[r][3]);
        *(float4*)(ph + 4) = make_float4(acc[r][4], acc[r][5], acc[r][6], acc[r][7]);

        uint32_t hp[4];
#pragma unroll
        for (int u = 0; u < 4; ++u) {
            __half h0 = __float2half_rn(acc[r][2 * u]);
            __half h1 = __float2half_rn(acc[r][2 * u + 1]);
            hp[u] = (uint32_t)__half_as_ushort(h0) |
                    ((uint32_t)__half_as_ushort(h1) << 16);
        }
        *(uint4*)(g_hh + (size_t)row * D + k0) = make_uint4(hp[0], hp[1], hp[2], hp[3]);

        float rsum = 0.f, ssum = 0.f, dsum = 0.f;
#pragma unroll
        for (int u = 0; u < 8; ++u) {
            rsum += acc[r][u];
            ssum = fmaf(acc[r][u], a_s[u], ssum);
            dsum = fmaf(acc[r][u], a_d[u], dsum);
        }
#pragma unroll
        for (int o = 8; o > 0; o >>= 1) {
            rsum += __shfl_down_sync(0xffffffffu, rsum, o, 16);
            ssum += __shfl_down_sync(0xffffffffu, ssum, o, 16);
            dsum += __shfl_down_sync(0xffffffffu, dsum, o, 16);
        }
        if ((lane & 15) == 0) {
            bool nz = (rsum != 0.0f);
            g_src[row] = ssum;
            g_Bz[row]  = nz ? __expf(dsum)        : 0.f;
            g_Cz[row]  = nz ? __expf(0.2f * dsum) : 0.f;
        }
    }
}

// ---------------- K2: softmax stats + bitmask (MLP=4) -----------------------
__global__ void k_stats(const int* __restrict__ adj) {
    int row  = blockIdx.x * SROWS + (threadIdx.x >> 5);
    int lane = threadIdx.x & 31;

    float src = g_src[row];
    float ea  = __expf(src);
    float eb  = __expf(0.2f * src);

    float s = 0.f, vm = 0.f;
    int   cnt = 0;
    const int4* arow = (const int4*)(adj + (size_t)row * N);
    unsigned* mrow = g_mask + (size_t)row * (N / 32);

    for (int blk4 = 0; blk4 < N / 512; ++blk4) {
        int4 av[4];
#pragma unroll
        for (int q = 0; q < 4; ++q)
            av[q] = arow[blk4 * 128 + q * 32 + lane];
#pragma unroll
        for (int q = 0; q < 4; ++q) {
            int blk = blk4 * 4 + q;
            int j0  = blk * 128 + lane * 4;
            float4 bz = __ldg((const float4*)(g_Bz + j0));
            float4 cz = __ldg((const float4*)(g_Cz + j0));

            unsigned nib = (av[q].x > 0) | ((av[q].y > 0) << 1) |
                           ((av[q].z > 0) << 2) | ((av[q].w > 0) << 3);
            unsigned v = nib;
            v |= __shfl_down_sync(0xffffffffu, v, 1) << 4;
            v |= __shfl_down_sync(0xffffffffu, v, 2) << 8;
            v |= __shfl_down_sync(0xffffffffu, v, 4) << 16;
            if ((lane & 7) == 0)
                mrow[blk * 4 + (lane >> 3)] = v;

            float ba[4] = {bz.x, bz.y, bz.z, bz.w};
            float ca[4] = {cz.x, cz.y, cz.z, cz.w};
#pragma unroll
            for (int u = 0; u < 4; ++u) {
                float vv  = fmaxf(ea * ba[u], eb * ca[u]);
                bool  bit = (nib >> u) & 1u;
                float val = bit ? vv : 0.f;
                s  += val;
                vm  = fmaxf(vm, val);
                cnt += (bit && vv > 0.f) ? 1 : 0;
            }
        }
    }
#pragma unroll
    for (int o = 16; o > 0; o >>= 1) {
        s   += __shfl_xor_sync(0xffffffffu, s, o);
        vm   = fmaxf(vm, __shfl_xor_sync(0xffffffffu, vm, o));
        cnt += __shfl_xor_sync(0xffffffffu, cnt, o);
    }
    if (lane == 0) {
        bool active = (vm > THR * s);
        float eaF = 0.f, ebF = 0.f, T3 = CUDART_INF_F;
        if (active) {
            float F = (float)cnt / s;
            eaF = ea * F;
            ebF = eb * F;
            T3  = THR * (float)cnt;
        }
        g_rowc[row] = make_float4(eaF, ebF, T3, 0.f);
    }
}

// ---------------- K3: persistent MMA kernel (fp16 1-pass, M=64, occ 3) ------
__global__ void __launch_bounds__(256, 3) k_agg() {
    extern __shared__ __align__(16) char sm[];
    __shared__ unsigned s_u;
    uint32_t smb = smem_u32(sm);

    int tid  = threadIdx.x;
    int lane = tid & 31;
    int wid  = tid >> 5;

    float* s_bz = (float*)(sm + SM_TAB);
    float* s_cz = s_bz + JR;

    int gi = tid >> 2;            // gen row within i-block (0..63)
    int j8 = (tid & 3) << 3;      // gen 8-j slice within BK
    int wm = (wid & 1) * 32;      // mma warp tile: 2 x 4 grid of 32x32
    int wn = (wid >> 1) * 32;

    while (true) {
        if (tid == 0) s_u = atomicAdd(&g_ctr, 1u);
        __syncthreads();
        unsigned u = s_u;
        if (u >= NUNITS) break;

        int split  = u >> 7;
        int iblk   = u & 127;
        int ib     = iblk * MB;
        int jstart = split * JR;

        float4 rc = g_rowc[ib + gi];
        const unsigned* mrow =
            g_mask + (size_t)(ib + gi) * (N / 32) + (jstart >> 5);

        float acc[2][4][4];
#pragma unroll
        for (int mf = 0; mf < 2; ++mf)
#pragma unroll
            for (int nf = 0; nf < 4; ++nf)
#pragma unroll
                for (int q = 0; q < 4; ++q) acc[mf][nf][q] = 0.f;

        auto loadB = [&](int t) {
            int b  = t & 1;
            int jb = jstart + t * BK;
            uint32_t Bh = smb + b * BUF_BYTES + A_BYTES;
#pragma unroll
            for (int q = 0; q < 2; ++q) {
                int idx = tid + q * 256;
                int r = idx >> 4, g = idx & 15;
                uint32_t doff = (uint32_t)(r * BPITCH + g * 8) * 2;
                cpa16(Bh + doff, g_hh + (size_t)(jb + r) * D + g * 8);
            }
            CPA_COMMIT();
        };

        auto gen_store = [&](int t, unsigned mw_full) {
            int b = t & 1;
            char* Ah = sm + b * BUF_BYTES;
            unsigned mw = mw_full >> j8;
            int lj = t * BK + j8;
            const float4* tb = (const float4*)(s_bz + lj);
            const float4* tc = (const float4*)(s_cz + lj);
            uint32_t* a32 = (uint32_t*)Ah + gi * (APITCH / 2) + (j8 >> 1);
#pragma unroll
            for (int e = 0; e < 2; ++e) {
                float4 bz = tb[e];
                float4 cz = tc[e];
                float ba[4] = {bz.x, bz.y, bz.z, bz.w};
                float ca[4] = {cz.x, cz.y, cz.z, cz.w};
                float w[4];
#pragma unroll
                for (int k = 0; k < 4; ++k) {
                    float v  = fmaxf(rc.x * ba[k], rc.y * ca[k]);
                    bool  ok = (v >= rc.z) && ((mw >> (e * 4 + k)) & 1u);
                    w[k] = ok ? v : 0.f;
                }
                uint32_t p0, p1;
                asm("cvt.rn.f16x2.f32 %0, %1, %2;" : "=r"(p0) : "f"(w[1]), "f"(w[0]));
                asm("cvt.rn.f16x2.f32 %0, %1, %2;" : "=r"(p1) : "f"(w[3]), "f"(w[2]));
                *(uint2*)&a32[e * 2] = make_uint2(p0, p1);
            }
        };

        auto domma = [&](int t) {
            int b = t & 1;
            uint32_t Ah = smb + b * BUF_BYTES;
            uint32_t Bh = Ah + A_BYTES;
#pragma unroll
            for (int ks = 0; ks < 2; ++ks) {
                int k0 = ks * 16;
                uint32_t af[2][4];
#pragma unroll
                for (int mf = 0; mf < 2; ++mf) {
                    uint32_t row = wm + mf * 16 + (lane & 15);
                    uint32_t off = row * (APITCH * 2) + (k0 + ((lane >> 4) << 3)) * 2;
                    ldsm4(af[mf], Ah + off);
                }
#pragma unroll
                for (int nf2 = 0; nf2 < 2; ++nf2) {
                    int n0 = wn + nf2 * 16;
                    uint32_t r = k0 + (lane & 7) + ((lane >> 3) & 1) * 8;
                    uint32_t c = n0 + ((lane >> 4) << 3);
                    uint32_t off = r * (BPITCH * 2) + c * 2;
                    uint32_t bh[4];
                    ldsm4t(bh, Bh + off);
#pragma unroll
                    for (int mf = 0; mf < 2; ++mf) {
                        mma16816(acc[mf][nf2 * 2],     af[mf], bh);
                        mma16816(acc[mf][nf2 * 2 + 1], af[mf], bh + 2);
                    }
                }
            }
        };

        // ---- unit prologue ---------------------------------------------------
        loadB(0);
        if (tid < 128)
            ((float4*)s_bz)[tid] = __ldg((const float4*)(g_Bz + jstart) + tid);
        else
            ((float4*)s_cz)[tid - 128] =
                __ldg((const float4*)(g_Cz + jstart) + (tid - 128));
        __syncthreads();
        gen_store(0, __ldg(&mrow[0]));

        // ---- pipeline --------------------------------------------------------
        for (int t = 0; t < NT; ++t) {
            CPA_WAIT0();
            __syncthreads();
            unsigned mwn = 0;
            if (t + 1 < NT) {
                mwn = __ldg(&mrow[t + 1]);
                loadB(t + 1);
            }
            domma(t);
            if (t + 1 < NT) gen_store(t + 1, mwn);
        }

        // ---- epilogue: write split partial -----------------------------------
        int r0    = ib + wm + (lane >> 2);
        int cbase = wn + (lane & 3) * 2;
#pragma unroll
        for (int mf = 0; mf < 2; ++mf)
#pragma unroll
            for (int nf = 0; nf < 4; ++nf) {
                int row = r0 + mf * 16;
                int col = cbase + nf * 8;
                float* p = &g_part[split][(size_t)row * D + col];
                *(float2*)p           = make_float2(acc[mf][nf][0], acc[mf][nf][1]);
                *(float2*)(p + 8 * D) = make_float2(acc[mf][nf][2], acc[mf][nf][3]);
            }
    }
}

// ---------------- K4: combine partials + residual + ELU ---------------------
__global__ void k_out(float* __restrict__ out) {
    int g = blockIdx.x * blockDim.x + threadIdx.x;
    float4 v = ((const float4*)g_h)[g];
#pragma unroll
    for (int s = 0; s < SPLIT; ++s) {
        float4 p = __ldg((const float4*)g_part[s] + g);
        v.x += p.x; v.y += p.y; v.z += p.z; v.w += p.w;
    }
    float4 o;
    o.x = (v.x > 0.f) ? v.x : expm1f(v.x);
    o.y = (v.y > 0.f) ? v.y : expm1f(v.y);
    o.z = (v.z > 0.f) ? v.z : expm1f(v.z);
    o.w = (v.w > 0.f) ? v.w : expm1f(v.w);
    ((float4*)out)[g] = o;
}

// ---------------- launch ----------------------------------------------------
extern "C" void kernel_launch(void* const* d_in, const int* in_sizes, int n_in,
                              void* d_out, int out_size) {
    (void)in_sizes; (void)n_in; (void)out_size;
    const float* x   = (const float*)d_in[0];
    const float* W   = (const float*)d_in[1];
    const float* a   = (const float*)d_in[2];
    const int*   adj = (const int*)d_in[3];
    float*       out = (float*)d_out;

    cudaFuncSetAttribute(k_h,   cudaFuncAttributeMaxDynamicSharedMemorySize, KH_SMEM);
    cudaFuncSetAttribute(k_agg, cudaFuncAttributeMaxDynamicSharedMemorySize, SMEM_DYN);

    k_h    <<<N / KH_ROWS, 256, KH_SMEM>>>(x, W, a);
    k_stats<<<N / SROWS, 256>>>(adj);
    k_agg  <<<NCTA, 256, SMEM_DYN>>>();
    k_out  <<<(N * D) / 1024, 256>>>(out);
}